// round 3
// baseline (speedup 1.0000x reference)
#include <cuda_runtime.h>
#include <cstdint>
#include <cstddef>

#define DIM    2048
#define BATCH  16384
#define TM     128          // == ghost-BN virtual batch
#define TN     256
#define KC     32
#define NCH    (DIM / KC)   // 64

// smem stage layout (bytes): bf16 tiles, 80B row stride (32 bf16 data + pad)
#define ROWB   80
#define ST_AHI 0
#define ST_ALO (ST_AHI + TM * ROWB)          // 10240
#define ST_BHI (ST_ALO + TM * ROWB)          // 20480
#define ST_BLO (ST_BHI + TN * ROWB)          // 40960
#define STAGE_SZ (ST_BLO + TN * ROWB)        // 61440

// epilogue staging: [128][258] fp32 + 2x[512] stats
#define C_STRIDE 258
#define C_BYTES  (TM * C_STRIDE * 4)         // 132096
#define SMEM_TOTAL (C_BYTES + 4096)

// ---------------- scratch ----------------
__device__ float g_x[(size_t)BATCH * DIM];   // BN-normalized GEMM output

// ---------------- helpers ----------------
__device__ __forceinline__ uint32_t smem_u32(const void* p) {
    uint32_t a;
    asm("{ .reg .u64 t; cvta.to.shared.u64 t, %1; cvt.u32.u64 %0, t; }" : "=r"(a) : "l"(p));
    return a;
}

// pack (lo, hi): lo -> bits[15:0], hi -> bits[31:16]
__device__ __forceinline__ uint32_t pack_bf16x2(float lo, float hi) {
    uint32_t r;
    asm("cvt.rn.bf16x2.f32 %0, %1, %2;" : "=r"(r) : "f"(hi), "f"(lo));
    return r;
}

__device__ __forceinline__ void ldsm_x4(uint32_t* r, uint32_t addr) {
    asm volatile("ldmatrix.sync.aligned.m8n8.x4.shared.b16 {%0,%1,%2,%3}, [%4];"
                 : "=r"(r[0]), "=r"(r[1]), "=r"(r[2]), "=r"(r[3]) : "r"(addr));
}

__device__ __forceinline__ void mma_bf16(float* c, const uint32_t* a, uint32_t b0, uint32_t b1) {
    asm volatile("mma.sync.aligned.m16n8k16.row.col.f32.bf16.bf16.f32 "
                 "{%0,%1,%2,%3}, {%4,%5,%6,%7}, {%8,%9}, {%0,%1,%2,%3};"
                 : "+f"(c[0]), "+f"(c[1]), "+f"(c[2]), "+f"(c[3])
                 : "r"(a[0]), "r"(a[1]), "r"(a[2]), "r"(a[3]), "r"(b0), "r"(b1));
}

// fp32 float4 -> two bf16x2 words (hi) + two (lo residual)
__device__ __forceinline__ void split4(float4 v, uint2& hi, uint2& lo) {
    uint32_t h0 = pack_bf16x2(v.x, v.y);
    uint32_t h1 = pack_bf16x2(v.z, v.w);
    float lx = v.x - __uint_as_float(h0 << 16);
    float ly = v.y - __uint_as_float(h0 & 0xffff0000u);
    float lz = v.z - __uint_as_float(h1 << 16);
    float lw = v.w - __uint_as_float(h1 & 0xffff0000u);
    hi = make_uint2(h0, h1);
    lo = make_uint2(pack_bf16x2(lx, ly), pack_bf16x2(lz, lw));
}

// ================= GEMM (mma.sync bf16 hi/lo x3) + fused GhostBN =================
__global__ void __launch_bounds__(512, 1)
gemm_bn_kernel(const float* __restrict__ feat, const float* __restrict__ wmat,
               const float* __restrict__ gamma, const float* __restrict__ beta)
{
    extern __shared__ __align__(16) char smem[];
    const uint32_t sbase = smem_u32(smem);
    const int tid  = threadIdx.x;
    const int lane = tid & 31;
    const int wid  = tid >> 5;          // 0..15
    const int wm   = wid >> 3;          // warp row 0..1 (64 rows each)
    const int wn   = wid & 7;           // warp col 0..7 (32 cols each)
    const int m0   = blockIdx.y * TM;
    const int n0   = blockIdx.x * TN;

    const float* Ag = feat + (size_t)m0 * DIM;
    const float* Bg = wmat + (size_t)n0 * DIM;

    float acc[4][4][4];
    #pragma unroll
    for (int i = 0; i < 4; ++i)
        #pragma unroll
        for (int j = 0; j < 4; ++j)
            #pragma unroll
            for (int k = 0; k < 4; ++k) acc[i][j][k] = 0.f;

    // precomputed ldmatrix base addresses (per-lane row mapping)
    const uint32_t a_row = (uint32_t)(wm * 64 + (lane & 15));
    const uint32_t a_col = (uint32_t)((lane >> 4) * 16);
    const uint32_t aHbase = sbase + ST_AHI + a_row * ROWB + a_col;
    const uint32_t aLbase = sbase + ST_ALO + a_row * ROWB + a_col;
    const uint32_t b_row = (uint32_t)(wn * 32 + (lane & 7) + ((lane >> 4) & 1) * 8);
    const uint32_t b_col = (uint32_t)(((lane >> 3) & 1) * 16);
    const uint32_t bHbase = sbase + ST_BHI + b_row * ROWB + b_col;
    const uint32_t bLbase = sbase + ST_BLO + b_row * ROWB + b_col;

    // prefetch chunk 0
    float4 va[2], vb[4];
    {
        #pragma unroll
        for (int i = 0; i < 2; ++i) {
            int item = tid + i * 512, r = item >> 3, q = item & 7;
            va[i] = *reinterpret_cast<const float4*>(Ag + (size_t)r * DIM + q * 4);
        }
        #pragma unroll
        for (int i = 0; i < 4; ++i) {
            int item = tid + i * 512, r = item >> 3, q = item & 7;
            vb[i] = *reinterpret_cast<const float4*>(Bg + (size_t)r * DIM + q * 4);
        }
    }

    for (int c = 0; c < NCH; ++c) {
        __syncthreads();                       // smem free (prev chunk's mma done)
        // convert + store staged regs
        #pragma unroll
        for (int i = 0; i < 2; ++i) {
            int item = tid + i * 512, r = item >> 3, q = item & 7;
            uint2 hi, lo; split4(va[i], hi, lo);
            *reinterpret_cast<uint2*>(smem + ST_AHI + r * ROWB + q * 8) = hi;
            *reinterpret_cast<uint2*>(smem + ST_ALO + r * ROWB + q * 8) = lo;
        }
        #pragma unroll
        for (int i = 0; i < 4; ++i) {
            int item = tid + i * 512, r = item >> 3, q = item & 7;
            uint2 hi, lo; split4(vb[i], hi, lo);
            *reinterpret_cast<uint2*>(smem + ST_BHI + r * ROWB + q * 8) = hi;
            *reinterpret_cast<uint2*>(smem + ST_BLO + r * ROWB + q * 8) = lo;
        }
        __syncthreads();                       // smem ready

        // prefetch next chunk (LDG latency hidden behind the MMAs below)
        if (c + 1 < NCH) {
            const int k0 = (c + 1) * KC;
            #pragma unroll
            for (int i = 0; i < 2; ++i) {
                int item = tid + i * 512, r = item >> 3, q = item & 7;
                va[i] = *reinterpret_cast<const float4*>(Ag + (size_t)r * DIM + k0 + q * 4);
            }
            #pragma unroll
            for (int i = 0; i < 4; ++i) {
                int item = tid + i * 512, r = item >> 3, q = item & 7;
                vb[i] = *reinterpret_cast<const float4*>(Bg + (size_t)r * DIM + k0 + q * 4);
            }
        }

        // MMA: 2 k16 steps x (hi*hi + lo*hi + hi*lo)
        #pragma unroll
        for (int ks = 0; ks < 2; ++ks) {
            const uint32_t kb = (uint32_t)(ks * 32);
            uint32_t ah[4][4], al[4][4], bb[2][4];
            #pragma unroll
            for (int mt = 0; mt < 4; ++mt) ldsm_x4(ah[mt], aHbase + mt * (16 * ROWB) + kb);
            #pragma unroll
            for (int bt = 0; bt < 2; ++bt) ldsm_x4(bb[bt], bHbase + bt * (16 * ROWB) + kb);
            #pragma unroll
            for (int mt = 0; mt < 4; ++mt)
                #pragma unroll
                for (int nt = 0; nt < 4; ++nt)
                    mma_bf16(acc[mt][nt], ah[mt], bb[nt >> 1][(nt & 1) * 2], bb[nt >> 1][(nt & 1) * 2 + 1]);
            #pragma unroll
            for (int mt = 0; mt < 4; ++mt) ldsm_x4(al[mt], aLbase + mt * (16 * ROWB) + kb);
            #pragma unroll
            for (int mt = 0; mt < 4; ++mt)
                #pragma unroll
                for (int nt = 0; nt < 4; ++nt)
                    mma_bf16(acc[mt][nt], al[mt], bb[nt >> 1][(nt & 1) * 2], bb[nt >> 1][(nt & 1) * 2 + 1]);
            #pragma unroll
            for (int bt = 0; bt < 2; ++bt) ldsm_x4(bb[bt], bLbase + bt * (16 * ROWB) + kb);
            #pragma unroll
            for (int mt = 0; mt < 4; ++mt)
                #pragma unroll
                for (int nt = 0; nt < 4; ++nt)
                    mma_bf16(acc[mt][nt], ah[mt], bb[nt >> 1][(nt & 1) * 2], bb[nt >> 1][(nt & 1) * 2 + 1]);
        }
    }
    __syncthreads();    // done with pipeline smem; reuse for epilogue

    // ---- stage C tile to smem ----
    float* sf = reinterpret_cast<float*>(smem);           // [128][258]
    {
        const int rbase = wm * 64 + (lane >> 2);
        const int cbase = wn * 32 + (lane & 3) * 2;
        #pragma unroll
        for (int mt = 0; mt < 4; ++mt)
            #pragma unroll
            for (int nt = 0; nt < 4; ++nt) {
                int r = rbase + mt * 16, cc = cbase + nt * 8;
                *reinterpret_cast<float2*>(&sf[r * C_STRIDE + cc]) =
                    make_float2(acc[mt][nt][0], acc[mt][nt][1]);
                *reinterpret_cast<float2*>(&sf[(r + 8) * C_STRIDE + cc]) =
                    make_float2(acc[mt][nt][2], acc[mt][nt][3]);
            }
    }
    __syncthreads();

    // ---- ghost-BN stats over the 128-row tile (per column) ----
    float* s_sum = reinterpret_cast<float*>(smem + C_BYTES);          // [512]
    float* s_sq  = s_sum + 512;
    {
        const int col = tid & 255, half = tid >> 8;
        float sum = 0.f, sq = 0.f;
        #pragma unroll 8
        for (int r = half * 64; r < half * 64 + 64; ++r) {
            float v = sf[r * C_STRIDE + col];
            sum += v; sq += v * v;
        }
        s_sum[tid] = sum; s_sq[tid] = sq;
    }
    __syncthreads();
    if (tid < 256) {
        float sum = s_sum[tid] + s_sum[tid + 256];
        float sq  = s_sq[tid] + s_sq[tid + 256];
        float mean = sum * (1.f / 128.f);
        float var  = fmaxf(sq * (1.f / 128.f) - mean * mean, 0.f);
        float sc = gamma[n0 + tid] * rsqrtf(var + 1e-5f);
        s_sum[tid] = sc;                         // scale
        s_sq[tid]  = beta[n0 + tid] - mean * sc; // shift
    }
    __syncthreads();

    // ---- normalized write ----
    float* orow = g_x + (size_t)m0 * DIM + n0;
    #pragma unroll 4
    for (int i = 0; i < 64; ++i) {
        int idx = tid + i * 512;
        int r = idx >> 8, cc = idx & 255;
        orow[(size_t)r * DIM + cc] = sf[r * C_STRIDE + cc] * s_sum[cc] + s_sq[cc];
    }
}

// ================= sparsemax (Michelot fixed point, row-per-block) =================
__device__ __forceinline__ float2 block_reduce2(float a, float b, float2* red, int tid) {
    #pragma unroll
    for (int o = 16; o > 0; o >>= 1) {
        a += __shfl_down_sync(0xffffffffu, a, o);
        b += __shfl_down_sync(0xffffffffu, b, o);
    }
    if ((tid & 31) == 0) red[tid >> 5] = make_float2(a, b);
    __syncthreads();
    if (tid < 32) {
        float2 v = (tid < 8) ? red[tid] : make_float2(0.f, 0.f);
        a = v.x; b = v.y;
        #pragma unroll
        for (int o = 4; o > 0; o >>= 1) {
            a += __shfl_down_sync(0xffffffffu, a, o);
            b += __shfl_down_sync(0xffffffffu, b, o);
        }
        if (tid == 0) red[0] = make_float2(a, b);
    }
    __syncthreads();
    float2 r = red[0];
    __syncthreads();
    return r;
}

__global__ void __launch_bounds__(256)
sparsemax_kernel(const float* __restrict__ priors, float* __restrict__ out)
{
    __shared__ float2 red[8];
    const int b = blockIdx.x;
    const int tid = threadIdx.x;
    const float* xr = g_x + (size_t)b * DIM;
    const float* pr = priors + (size_t)b * DIM;

    float z[8];
    float s = 0.f;
    #pragma unroll
    for (int i = 0; i < 8; ++i) {
        int j = tid + i * 256;
        z[i] = xr[j] * pr[j];
        s += z[i];
    }
    float2 tot = block_reduce2(s, 0.f, red, tid);
    float tau = (tot.x - 1.f) * (1.f / (float)DIM);

    for (int it = 0; it < 48; ++it) {
        float ps = 0.f, pc = 0.f;
        #pragma unroll
        for (int i = 0; i < 8; ++i)
            if (z[i] > tau) { ps += z[i]; pc += 1.f; }
        float2 r = block_reduce2(ps, pc, red, tid);
        float tn = (r.x - 1.f) / r.y;
        if (tn == tau) break;   // uniform across block (same reduced inputs)
        tau = tn;
    }
    #pragma unroll
    for (int i = 0; i < 8; ++i) {
        int j = tid + i * 256;
        out[(size_t)b * DIM + j] = fmaxf(z[i] - tau, 0.f);
    }
}

// ================= launch =================
extern "C" void kernel_launch(void* const* d_in, const int* in_sizes, int n_in,
                              void* d_out, int out_size)
{
    const float* priors = (const float*)d_in[0];
    const float* feat   = (const float*)d_in[1];
    const float* fw     = (const float*)d_in[2];
    const float* gamma  = (const float*)d_in[3];
    const float* beta   = (const float*)d_in[4];
    float* out = (float*)d_out;

    static bool attr_set = false;
    if (!attr_set) {
        cudaFuncSetAttribute(gemm_bn_kernel, cudaFuncAttributeMaxDynamicSharedMemorySize, SMEM_TOTAL);
        attr_set = true;
    }

    dim3 grid(DIM / TN, BATCH / TM);    // (8, 128); x fastest keeps W in L2
    gemm_bn_kernel<<<grid, 512, SMEM_TOTAL>>>(feat, fw, gamma, beta);
    sparsemax_kernel<<<BATCH, 256>>>(priors, out);
}

// round 4
// speedup vs baseline: 1.1486x; 1.1486x over previous
#include <cuda_runtime.h>
#include <cstdint>
#include <cstddef>

#define DIM    2048
#define BATCH  16384
#define TM     128          // == ghost-BN virtual batch
#define TN     256
#define KC     32
#define NCH    (DIM / KC)   // 64
#define NSTAGE 3

// smem per-stage layout (bytes): bf16 tiles, 80B row stride (64B data + pad)
#define ROWB   80
#define ST_AHI 0
#define ST_ALO (ST_AHI + TM * ROWB)          // 10240
#define ST_BHI (ST_ALO + TM * ROWB)          // 20480
#define ST_BLO (ST_BHI + TN * ROWB)          // 40960
#define STAGE_SZ (ST_BLO + TN * ROWB)        // 61440
#define SMEM_TOTAL (NSTAGE * STAGE_SZ)       // 184320

// epilogue staging: [128][258] fp32 + 2x[512] stats (reuses pipeline smem)
#define C_STRIDE 258
#define C_BYTES  (TM * C_STRIDE * 4)         // 132096 (< SMEM_TOTAL)

// ---------------- scratch ----------------
__device__ float g_x[(size_t)BATCH * DIM];              // BN-normalized GEMM output
__device__ uint2 g_ahi[(size_t)BATCH * DIM / 4];        // feat hi (bf16 x4 per uint2)
__device__ uint2 g_alo[(size_t)BATCH * DIM / 4];        // feat lo residual
__device__ uint2 g_bhi[(size_t)DIM * DIM / 4];          // W hi
__device__ uint2 g_blo[(size_t)DIM * DIM / 4];          // W lo

// ---------------- helpers ----------------
__device__ __forceinline__ uint32_t smem_u32(const void* p) {
    uint32_t a;
    asm("{ .reg .u64 t; cvta.to.shared.u64 t, %1; cvt.u32.u64 %0, t; }" : "=r"(a) : "l"(p));
    return a;
}

// pack (lo, hi): lo -> bits[15:0], hi -> bits[31:16]
__device__ __forceinline__ uint32_t pack_bf16x2(float lo, float hi) {
    uint32_t r;
    asm("cvt.rn.bf16x2.f32 %0, %1, %2;" : "=r"(r) : "f"(hi), "f"(lo));
    return r;
}

__device__ __forceinline__ void ldsm_x4(uint32_t* r, uint32_t addr) {
    asm volatile("ldmatrix.sync.aligned.m8n8.x4.shared.b16 {%0,%1,%2,%3}, [%4];"
                 : "=r"(r[0]), "=r"(r[1]), "=r"(r[2]), "=r"(r[3]) : "r"(addr));
}

__device__ __forceinline__ void mma_bf16(float* c, const uint32_t* a, uint32_t b0, uint32_t b1) {
    asm volatile("mma.sync.aligned.m16n8k16.row.col.f32.bf16.bf16.f32 "
                 "{%0,%1,%2,%3}, {%4,%5,%6,%7}, {%8,%9}, {%0,%1,%2,%3};"
                 : "+f"(c[0]), "+f"(c[1]), "+f"(c[2]), "+f"(c[3])
                 : "r"(a[0]), "r"(a[1]), "r"(a[2]), "r"(a[3]), "r"(b0), "r"(b1));
}

__device__ __forceinline__ void cp16(uint32_t dst, const void* src) {
    asm volatile("cp.async.cg.shared.global [%0], [%1], 16;" :: "r"(dst), "l"(src));
}
#define CP_COMMIT() asm volatile("cp.async.commit_group;" ::: "memory")
#define CP_WAIT1()  asm volatile("cp.async.wait_group 1;" ::: "memory")

// fp32 float4 -> two bf16x2 words (hi) + two (lo residual)
__device__ __forceinline__ void split4(float4 v, uint2& hi, uint2& lo) {
    uint32_t h0 = pack_bf16x2(v.x, v.y);
    uint32_t h1 = pack_bf16x2(v.z, v.w);
    float lx = v.x - __uint_as_float(h0 << 16);
    float ly = v.y - __uint_as_float(h0 & 0xffff0000u);
    float lz = v.z - __uint_as_float(h1 << 16);
    float lw = v.w - __uint_as_float(h1 & 0xffff0000u);
    hi = make_uint2(h0, h1);
    lo = make_uint2(pack_bf16x2(lx, ly), pack_bf16x2(lz, lw));
}

// ================= kernel 0: fp32 -> bf16 hi/lo split =================
#define FEAT_N4 ((BATCH * DIM) / 4)
#define W_N4    ((DIM * DIM) / 4)

__global__ void __launch_bounds__(256)
split_kernel(const float* __restrict__ feat, const float* __restrict__ wmat)
{
    int idx = blockIdx.x * 256 + threadIdx.x;
    if (idx < FEAT_N4) {
        uint2 hi, lo;
        split4(reinterpret_cast<const float4*>(feat)[idx], hi, lo);
        g_ahi[idx] = hi; g_alo[idx] = lo;
    } else if (idx < FEAT_N4 + W_N4) {
        int j = idx - FEAT_N4;
        uint2 hi, lo;
        split4(reinterpret_cast<const float4*>(wmat)[j], hi, lo);
        g_bhi[j] = hi; g_blo[j] = lo;
    }
}

// ================= kernel 1: GEMM (mma.sync bf16 x3) + fused GhostBN =================
__global__ void __launch_bounds__(512, 1)
gemm_bn_kernel(const float* __restrict__ gamma, const float* __restrict__ beta)
{
    extern __shared__ __align__(16) char smem[];
    const uint32_t sbase = smem_u32(smem);
    const int tid  = threadIdx.x;
    const int lane = tid & 31;
    const int wid  = tid >> 5;          // 0..15
    const int wm   = wid >> 3;          // warp row 0..1 (64 rows each)
    const int wn   = wid & 7;           // warp col 0..7 (32 cols each)
    const int m0   = blockIdx.y * TM;
    const int n0   = blockIdx.x * TN;

    // per-thread cp.async coordinates (16B chunks; 64B of data per tile row)
    const int cr = tid >> 2, cq = tid & 3;                    // A: 1 chunk/thread
    const char* pAhi = (const char*)g_ahi + ((size_t)(m0 + cr) * DIM + cq * 8) * 2;
    const char* pAlo = (const char*)g_alo + ((size_t)(m0 + cr) * DIM + cq * 8) * 2;
    const uint32_t dA = (uint32_t)(cr * ROWB + cq * 16);
    const int br0 = tid >> 2,        bq0 = tid & 3;           // B: 2 chunks/thread
    const int br1 = (tid + 512) >> 2, bq1 = tid & 3;
    const char* pB0hi = (const char*)g_bhi + ((size_t)(n0 + br0) * DIM + bq0 * 8) * 2;
    const char* pB0lo = (const char*)g_blo + ((size_t)(n0 + br0) * DIM + bq0 * 8) * 2;
    const char* pB1hi = (const char*)g_bhi + ((size_t)(n0 + br1) * DIM + bq1 * 8) * 2;
    const char* pB1lo = (const char*)g_blo + ((size_t)(n0 + br1) * DIM + bq1 * 8) * 2;
    const uint32_t dB0 = (uint32_t)(br0 * ROWB + bq0 * 16);
    const uint32_t dB1 = (uint32_t)(br1 * ROWB + bq1 * 16);

    float acc[4][4][4];
    #pragma unroll
    for (int i = 0; i < 4; ++i)
        #pragma unroll
        for (int j = 0; j < 4; ++j)
            #pragma unroll
            for (int k = 0; k < 4; ++k) acc[i][j][k] = 0.f;

    // per-lane ldmatrix offsets (within a stage)
    const uint32_t a_off = (uint32_t)((wm * 64 + (lane & 15)) * ROWB + (lane >> 4) * 16);
    const uint32_t b_off = (uint32_t)((wn * 32 + (lane & 7) + ((lane >> 4) & 1) * 8) * ROWB
                                      + ((lane >> 3) & 1) * 16);

    // prologue: stages 0,1 in flight
    #pragma unroll
    for (int s = 0; s < 2; ++s) {
        const size_t kb = (size_t)(s * KC) * 2;   // byte offset along K
        const uint32_t sb = sbase + s * STAGE_SZ;
        cp16(sb + ST_AHI + dA,  pAhi + kb);
        cp16(sb + ST_ALO + dA,  pAlo + kb);
        cp16(sb + ST_BHI + dB0, pB0hi + kb);
        cp16(sb + ST_BHI + dB1, pB1hi + kb);
        cp16(sb + ST_BLO + dB0, pB0lo + kb);
        cp16(sb + ST_BLO + dB1, pB1lo + kb);
        CP_COMMIT();
    }

    int s_cur = 0, s_nxt = 2;
    for (int c = 0; c < NCH; ++c) {
        CP_WAIT1();
        __syncthreads();                          // stage s_cur ready; stage s_nxt free

        if (c + 2 < NCH) {
            const size_t kb = (size_t)((c + 2) * KC) * 2;
            const uint32_t sb = sbase + s_nxt * STAGE_SZ;
            cp16(sb + ST_AHI + dA,  pAhi + kb);
            cp16(sb + ST_ALO + dA,  pAlo + kb);
            cp16(sb + ST_BHI + dB0, pB0hi + kb);
            cp16(sb + ST_BHI + dB1, pB1hi + kb);
            cp16(sb + ST_BLO + dB0, pB0lo + kb);
            cp16(sb + ST_BLO + dB1, pB1lo + kb);
        }
        CP_COMMIT();

        const uint32_t st = sbase + s_cur * STAGE_SZ;
        #pragma unroll
        for (int ks = 0; ks < 2; ++ks) {
            const uint32_t kb = (uint32_t)(ks * 32);
            uint32_t ah[4][4], al[4][4], bb[2][4];
            #pragma unroll
            for (int mt = 0; mt < 4; ++mt) ldsm_x4(ah[mt], st + ST_AHI + a_off + mt * (16 * ROWB) + kb);
            #pragma unroll
            for (int bt = 0; bt < 2; ++bt) ldsm_x4(bb[bt], st + ST_BHI + b_off + bt * (16 * ROWB) + kb);
            #pragma unroll
            for (int mt = 0; mt < 4; ++mt)
                #pragma unroll
                for (int nt = 0; nt < 4; ++nt)
                    mma_bf16(acc[mt][nt], ah[mt], bb[nt >> 1][(nt & 1) * 2], bb[nt >> 1][(nt & 1) * 2 + 1]);
            #pragma unroll
            for (int mt = 0; mt < 4; ++mt) ldsm_x4(al[mt], st + ST_ALO + a_off + mt * (16 * ROWB) + kb);
            #pragma unroll
            for (int mt = 0; mt < 4; ++mt)
                #pragma unroll
                for (int nt = 0; nt < 4; ++nt)
                    mma_bf16(acc[mt][nt], al[mt], bb[nt >> 1][(nt & 1) * 2], bb[nt >> 1][(nt & 1) * 2 + 1]);
            #pragma unroll
            for (int bt = 0; bt < 2; ++bt) ldsm_x4(bb[bt], st + ST_BLO + b_off + bt * (16 * ROWB) + kb);
            #pragma unroll
            for (int mt = 0; mt < 4; ++mt)
                #pragma unroll
                for (int nt = 0; nt < 4; ++nt)
                    mma_bf16(acc[mt][nt], ah[mt], bb[nt >> 1][(nt & 1) * 2], bb[nt >> 1][(nt & 1) * 2 + 1]);
        }
        s_cur = (s_cur + 1) % NSTAGE;
        s_nxt = (s_nxt + 1) % NSTAGE;
    }
    __syncthreads();    // pipeline smem free; reuse for epilogue

    // ---- stage C tile to smem ----
    float* sf = reinterpret_cast<float*>(smem);           // [128][258]
    {
        const int rbase = wm * 64 + (lane >> 2);
        const int cbase = wn * 32 + (lane & 3) * 2;
        #pragma unroll
        for (int mt = 0; mt < 4; ++mt)
            #pragma unroll
            for (int nt = 0; nt < 4; ++nt) {
                int r = rbase + mt * 16, cc = cbase + nt * 8;
                *reinterpret_cast<float2*>(&sf[r * C_STRIDE + cc]) =
                    make_float2(acc[mt][nt][0], acc[mt][nt][1]);
                *reinterpret_cast<float2*>(&sf[(r + 8) * C_STRIDE + cc]) =
                    make_float2(acc[mt][nt][2], acc[mt][nt][3]);
            }
    }
    __syncthreads();

    // ---- ghost-BN stats over the 128-row tile (per column) ----
    float* s_sum = reinterpret_cast<float*>(smem + C_BYTES);          // [512]
    float* s_sq  = s_sum + 512;
    {
        const int col = tid & 255, half = tid >> 8;
        float sum = 0.f, sq = 0.f;
        #pragma unroll 8
        for (int r = half * 64; r < half * 64 + 64; ++r) {
            float v = sf[r * C_STRIDE + col];
            sum += v; sq += v * v;
        }
        s_sum[tid] = sum; s_sq[tid] = sq;
    }
    __syncthreads();
    if (tid < 256) {
        float sum = s_sum[tid] + s_sum[tid + 256];
        float sq  = s_sq[tid] + s_sq[tid + 256];
        float mean = sum * (1.f / 128.f);
        float var  = fmaxf(sq * (1.f / 128.f) - mean * mean, 0.f);
        float sc = gamma[n0 + tid] * rsqrtf(var + 1e-5f);
        s_sum[tid] = sc;                         // scale
        s_sq[tid]  = beta[n0 + tid] - mean * sc; // shift
    }
    __syncthreads();

    float* orow = g_x + (size_t)m0 * DIM + n0;
    #pragma unroll 4
    for (int i = 0; i < 64; ++i) {
        int idx = tid + i * 512;
        int r = idx >> 8, cc = idx & 255;
        orow[(size_t)r * DIM + cc] = sf[r * C_STRIDE + cc] * s_sum[cc] + s_sq[cc];
    }
}

// ================= kernel 2: sparsemax (warp-per-row Michelot) =================
__device__ __forceinline__ float warp_sum(float v) {
    #pragma unroll
    for (int o = 16; o > 0; o >>= 1) v += __shfl_xor_sync(0xffffffffu, v, o);
    return v;
}

__global__ void __launch_bounds__(256)
sparsemax_kernel(const float* __restrict__ priors, float* __restrict__ out)
{
    const int lane = threadIdx.x & 31;
    const int row  = blockIdx.x * 8 + (threadIdx.x >> 5);
    const float* xr = g_x + (size_t)row * DIM;
    const float* pr = priors + (size_t)row * DIM;

    float z[64];
    float s = 0.f;
    #pragma unroll
    for (int i = 0; i < 64; ++i) {
        int j = lane + i * 32;
        z[i] = xr[j] * pr[j];
        s += z[i];
    }
    float tau = (warp_sum(s) - 1.f) * (1.f / (float)DIM);

    for (int it = 0; it < 40; ++it) {
        float ps = 0.f, pc = 0.f;
        #pragma unroll
        for (int i = 0; i < 64; ++i)
            if (z[i] > tau) { ps += z[i]; pc += 1.f; }
        ps = warp_sum(ps); pc = warp_sum(pc);
        float tn = (ps - 1.f) / pc;
        if (tn == tau) break;        // warp-uniform (same reduced values)
        tau = tn;
    }
    #pragma unroll
    for (int i = 0; i < 64; ++i) {
        int j = lane + i * 32;
        out[(size_t)row * DIM + j] = fmaxf(z[i] - tau, 0.f);
    }
}

// ================= launch =================
extern "C" void kernel_launch(void* const* d_in, const int* in_sizes, int n_in,
                              void* d_out, int out_size)
{
    const float* priors = (const float*)d_in[0];
    const float* feat   = (const float*)d_in[1];
    const float* fw     = (const float*)d_in[2];
    const float* gamma  = (const float*)d_in[3];
    const float* beta   = (const float*)d_in[4];
    float* out = (float*)d_out;

    static bool attr_set = false;
    if (!attr_set) {
        cudaFuncSetAttribute(gemm_bn_kernel, cudaFuncAttributeMaxDynamicSharedMemorySize, SMEM_TOTAL);
        attr_set = true;
    }

    split_kernel<<<(FEAT_N4 + W_N4 + 255) / 256, 256>>>(feat, fw);
    dim3 grid(DIM / TN, BATCH / TM);    // (8, 128); x fastest keeps W in L2
    gemm_bn_kernel<<<grid, 512, SMEM_TOTAL>>>(gamma, beta);
    sparsemax_kernel<<<BATCH / 8, 256>>>(priors, out);
}

// round 5
// speedup vs baseline: 1.1998x; 1.0446x over previous
#include <cuda_runtime.h>
#include <cstdint>
#include <cstddef>

#define DIM    2048
#define BATCH  16384
#define TM     128          // == ghost-BN virtual batch
#define TN     256
#define KC     32
#define NCH    (DIM / KC)   // 64
#define NSTAGE 3

// smem per-stage layout (bytes): bf16 tiles, 80B row stride (64B data + pad)
#define ROWB   80
#define ST_AHI 0
#define ST_ALO (ST_AHI + TM * ROWB)          // 10240
#define ST_BHI (ST_ALO + TM * ROWB)          // 20480
#define ST_BLO (ST_BHI + TN * ROWB)          // 40960
#define STAGE_SZ (ST_BLO + TN * ROWB)        // 61440
#define SMEM_TOTAL (NSTAGE * STAGE_SZ)       // 184320

// epilogue staging: [128][258] fp32 + 2x[512] stats (reuses pipeline smem)
#define C_STRIDE 258
#define C_BYTES  (TM * C_STRIDE * 4)         // 132096 (< SMEM_TOTAL)

// ---------------- scratch ----------------
__device__ float g_x[(size_t)BATCH * DIM];              // BN-normalized GEMM output
__device__ uint2 g_ahi[(size_t)BATCH * DIM / 4];        // feat hi (bf16 x4 per uint2)
__device__ uint2 g_alo[(size_t)BATCH * DIM / 4];        // feat lo residual
__device__ uint2 g_bhi[(size_t)DIM * DIM / 4];          // W hi
__device__ uint2 g_blo[(size_t)DIM * DIM / 4];          // W lo

// ---------------- helpers ----------------
__device__ __forceinline__ uint32_t smem_u32(const void* p) {
    uint32_t a;
    asm("{ .reg .u64 t; cvta.to.shared.u64 t, %1; cvt.u32.u64 %0, t; }" : "=r"(a) : "l"(p));
    return a;
}

// pack (lo, hi): lo -> bits[15:0], hi -> bits[31:16]
__device__ __forceinline__ uint32_t pack_bf16x2(float lo, float hi) {
    uint32_t r;
    asm("cvt.rn.bf16x2.f32 %0, %1, %2;" : "=r"(r) : "f"(hi), "f"(lo));
    return r;
}

__device__ __forceinline__ void ldsm_x4(uint32_t* r, uint32_t addr) {
    asm volatile("ldmatrix.sync.aligned.m8n8.x4.shared.b16 {%0,%1,%2,%3}, [%4];"
                 : "=r"(r[0]), "=r"(r[1]), "=r"(r[2]), "=r"(r[3]) : "r"(addr));
}

__device__ __forceinline__ void mma_bf16(float* c, const uint32_t* a, uint32_t b0, uint32_t b1) {
    asm volatile("mma.sync.aligned.m16n8k16.row.col.f32.bf16.bf16.f32 "
                 "{%0,%1,%2,%3}, {%4,%5,%6,%7}, {%8,%9}, {%0,%1,%2,%3};"
                 : "+f"(c[0]), "+f"(c[1]), "+f"(c[2]), "+f"(c[3])
                 : "r"(a[0]), "r"(a[1]), "r"(a[2]), "r"(a[3]), "r"(b0), "r"(b1));
}

__device__ __forceinline__ void cp16(uint32_t dst, const void* src) {
    asm volatile("cp.async.cg.shared.global [%0], [%1], 16;" :: "r"(dst), "l"(src));
}
#define CP_COMMIT() asm volatile("cp.async.commit_group;" ::: "memory")
#define CP_WAIT1()  asm volatile("cp.async.wait_group 1;" ::: "memory")

// fp32 float4 -> two bf16x2 words (hi) + two (lo residual)
__device__ __forceinline__ void split4(float4 v, uint2& hi, uint2& lo) {
    uint32_t h0 = pack_bf16x2(v.x, v.y);
    uint32_t h1 = pack_bf16x2(v.z, v.w);
    float lx = v.x - __uint_as_float(h0 << 16);
    float ly = v.y - __uint_as_float(h0 & 0xffff0000u);
    float lz = v.z - __uint_as_float(h1 << 16);
    float lw = v.w - __uint_as_float(h1 & 0xffff0000u);
    hi = make_uint2(h0, h1);
    lo = make_uint2(pack_bf16x2(lx, ly), pack_bf16x2(lz, lw));
}

// ================= kernel 0: fp32 -> bf16 hi/lo split =================
#define FEAT_N4 ((BATCH * DIM) / 4)
#define W_N4    ((DIM * DIM) / 4)

__global__ void __launch_bounds__(256)
split_kernel(const float* __restrict__ feat, const float* __restrict__ wmat)
{
    int idx = blockIdx.x * 256 + threadIdx.x;
    if (idx < FEAT_N4) {
        uint2 hi, lo;
        split4(reinterpret_cast<const float4*>(feat)[idx], hi, lo);
        g_ahi[idx] = hi; g_alo[idx] = lo;
    } else if (idx < FEAT_N4 + W_N4) {
        int j = idx - FEAT_N4;
        uint2 hi, lo;
        split4(reinterpret_cast<const float4*>(wmat)[j], hi, lo);
        g_bhi[j] = hi; g_blo[j] = lo;
    }
}

// ================= kernel 1: GEMM (mma.sync bf16 x3) + fused GhostBN =================
__global__ void __launch_bounds__(512, 1)
gemm_bn_kernel(const float* __restrict__ gamma, const float* __restrict__ beta)
{
    extern __shared__ __align__(16) char smem[];
    const uint32_t sbase = smem_u32(smem);
    const int tid  = threadIdx.x;
    const int lane = tid & 31;
    const int wid  = tid >> 5;          // 0..15
    const int wm   = wid >> 3;          // warp row 0..1 (64 rows each)
    const int wn   = wid & 7;           // warp col 0..7 (32 cols each)
    const int m0   = blockIdx.y * TM;
    const int n0   = blockIdx.x * TN;

    // per-thread cp.async coordinates (16B chunks; 64B of data per tile row)
    const int cr = tid >> 2, cq = tid & 3;                    // A: 1 chunk/thread
    const char* pAhi = (const char*)g_ahi + ((size_t)(m0 + cr) * DIM + cq * 8) * 2;
    const char* pAlo = (const char*)g_alo + ((size_t)(m0 + cr) * DIM + cq * 8) * 2;
    const uint32_t dA = (uint32_t)(cr * ROWB + cq * 16);
    const int br0 = tid >> 2,         bq0 = tid & 3;          // B: 2 chunks/thread
    const int br1 = (tid + 512) >> 2, bq1 = tid & 3;
    const char* pB0hi = (const char*)g_bhi + ((size_t)(n0 + br0) * DIM + bq0 * 8) * 2;
    const char* pB0lo = (const char*)g_blo + ((size_t)(n0 + br0) * DIM + bq0 * 8) * 2;
    const char* pB1hi = (const char*)g_bhi + ((size_t)(n0 + br1) * DIM + bq1 * 8) * 2;
    const char* pB1lo = (const char*)g_blo + ((size_t)(n0 + br1) * DIM + bq1 * 8) * 2;
    const uint32_t dB0 = (uint32_t)(br0 * ROWB + bq0 * 16);
    const uint32_t dB1 = (uint32_t)(br1 * ROWB + bq1 * 16);

    float acc[4][4][4];
    #pragma unroll
    for (int i = 0; i < 4; ++i)
        #pragma unroll
        for (int j = 0; j < 4; ++j)
            #pragma unroll
            for (int k = 0; k < 4; ++k) acc[i][j][k] = 0.f;

    // per-lane ldmatrix offsets (within a stage)
    const uint32_t a_off = (uint32_t)((wm * 64 + (lane & 15)) * ROWB + (lane >> 4) * 16);
    const uint32_t b_off = (uint32_t)((wn * 32 + (lane & 7) + ((lane >> 4) & 1) * 8) * ROWB
                                      + ((lane >> 3) & 1) * 16);

    // prologue: stages 0,1 in flight
    #pragma unroll
    for (int s = 0; s < 2; ++s) {
        const size_t kb = (size_t)(s * KC) * 2;   // byte offset along K
        const uint32_t sb = sbase + s * STAGE_SZ;
        cp16(sb + ST_AHI + dA,  pAhi + kb);
        cp16(sb + ST_ALO + dA,  pAlo + kb);
        cp16(sb + ST_BHI + dB0, pB0hi + kb);
        cp16(sb + ST_BHI + dB1, pB1hi + kb);
        cp16(sb + ST_BLO + dB0, pB0lo + kb);
        cp16(sb + ST_BLO + dB1, pB1lo + kb);
        CP_COMMIT();
    }

    int s_cur = 0, s_nxt = 2;
    for (int c = 0; c < NCH; ++c) {
        CP_WAIT1();
        __syncthreads();                          // stage s_cur ready; stage s_nxt free

        if (c + 2 < NCH) {
            const size_t kb = (size_t)((c + 2) * KC) * 2;
            const uint32_t sb = sbase + s_nxt * STAGE_SZ;
            cp16(sb + ST_AHI + dA,  pAhi + kb);
            cp16(sb + ST_ALO + dA,  pAlo + kb);
            cp16(sb + ST_BHI + dB0, pB0hi + kb);
            cp16(sb + ST_BHI + dB1, pB1hi + kb);
            cp16(sb + ST_BLO + dB0, pB0lo + kb);
            cp16(sb + ST_BLO + dB1, pB1lo + kb);
        }
        CP_COMMIT();

        const uint32_t st = sbase + s_cur * STAGE_SZ;
        #pragma unroll
        for (int ks = 0; ks < 2; ++ks) {
            const uint32_t kb = (uint32_t)(ks * 32);
            // fragment registers: af reused for A_hi then A_lo -> peak live 96
            uint32_t af[4][4], bh[2][4], bl[2][4];
            #pragma unroll
            for (int mt = 0; mt < 4; ++mt) ldsm_x4(af[mt], st + ST_AHI + a_off + mt * (16 * ROWB) + kb);
            #pragma unroll
            for (int bt = 0; bt < 2; ++bt) ldsm_x4(bh[bt], st + ST_BHI + b_off + bt * (16 * ROWB) + kb);
            #pragma unroll
            for (int bt = 0; bt < 2; ++bt) ldsm_x4(bl[bt], st + ST_BLO + b_off + bt * (16 * ROWB) + kb);
            // P1: A_hi * B_hi
            #pragma unroll
            for (int mt = 0; mt < 4; ++mt)
                #pragma unroll
                for (int nt = 0; nt < 4; ++nt)
                    mma_bf16(acc[mt][nt], af[mt], bh[nt >> 1][(nt & 1) * 2], bh[nt >> 1][(nt & 1) * 2 + 1]);
            // P2: A_hi * B_lo   (A_hi dies after this pass)
            #pragma unroll
            for (int mt = 0; mt < 4; ++mt)
                #pragma unroll
                for (int nt = 0; nt < 4; ++nt)
                    mma_bf16(acc[mt][nt], af[mt], bl[nt >> 1][(nt & 1) * 2], bl[nt >> 1][(nt & 1) * 2 + 1]);
            // reload af <- A_lo (reuses the same registers)
            #pragma unroll
            for (int mt = 0; mt < 4; ++mt) ldsm_x4(af[mt], st + ST_ALO + a_off + mt * (16 * ROWB) + kb);
            // P3: A_lo * B_hi
            #pragma unroll
            for (int mt = 0; mt < 4; ++mt)
                #pragma unroll
                for (int nt = 0; nt < 4; ++nt)
                    mma_bf16(acc[mt][nt], af[mt], bh[nt >> 1][(nt & 1) * 2], bh[nt >> 1][(nt & 1) * 2 + 1]);
        }
        s_cur = (s_cur + 1) % NSTAGE;
        s_nxt = (s_nxt + 1) % NSTAGE;
    }
    __syncthreads();    // pipeline smem free; reuse for epilogue

    // ---- stage C tile to smem ----
    float* sf = reinterpret_cast<float*>(smem);           // [128][258]
    {
        const int rbase = wm * 64 + (lane >> 2);
        const int cbase = wn * 32 + (lane & 3) * 2;
        #pragma unroll
        for (int mt = 0; mt < 4; ++mt)
            #pragma unroll
            for (int nt = 0; nt < 4; ++nt) {
                int r = rbase + mt * 16, cc = cbase + nt * 8;
                *reinterpret_cast<float2*>(&sf[r * C_STRIDE + cc]) =
                    make_float2(acc[mt][nt][0], acc[mt][nt][1]);
                *reinterpret_cast<float2*>(&sf[(r + 8) * C_STRIDE + cc]) =
                    make_float2(acc[mt][nt][2], acc[mt][nt][3]);
            }
    }
    __syncthreads();

    // ---- ghost-BN stats over the 128-row tile (per column) ----
    float* s_sum = reinterpret_cast<float*>(smem + C_BYTES);          // [512]
    float* s_sq  = s_sum + 512;
    {
        const int col = tid & 255, half = tid >> 8;
        float sum = 0.f, sq = 0.f;
        #pragma unroll 8
        for (int r = half * 64; r < half * 64 + 64; ++r) {
            float v = sf[r * C_STRIDE + col];
            sum += v; sq += v * v;
        }
        s_sum[tid] = sum; s_sq[tid] = sq;
    }
    __syncthreads();
    if (tid < 256) {
        float sum = s_sum[tid] + s_sum[tid + 256];
        float sq  = s_sq[tid] + s_sq[tid + 256];
        float mean = sum * (1.f / 128.f);
        float var  = fmaxf(sq * (1.f / 128.f) - mean * mean, 0.f);
        float sc = gamma[n0 + tid] * rsqrtf(var + 1e-5f);
        s_sum[tid] = sc;                         // scale
        s_sq[tid]  = beta[n0 + tid] - mean * sc; // shift
    }
    __syncthreads();

    // ---- normalized write (float4) ----
    float* orow = g_x + (size_t)m0 * DIM + n0;
    #pragma unroll
    for (int i = 0; i < 16; ++i) {
        int idx = tid + i * 512;                 // 8192 float4s
        int r = idx >> 6, c4 = (idx & 63) * 4;
        float4 v;
        v.x = sf[r * C_STRIDE + c4 + 0] * s_sum[c4 + 0] + s_sq[c4 + 0];
        v.y = sf[r * C_STRIDE + c4 + 1] * s_sum[c4 + 1] + s_sq[c4 + 1];
        v.z = sf[r * C_STRIDE + c4 + 2] * s_sum[c4 + 2] + s_sq[c4 + 2];
        v.w = sf[r * C_STRIDE + c4 + 3] * s_sum[c4 + 3] + s_sq[c4 + 3];
        *reinterpret_cast<float4*>(&orow[(size_t)r * DIM + c4]) = v;
    }
}

// ================= kernel 2: sparsemax (warp-per-row Michelot) =================
__device__ __forceinline__ float warp_sum(float v) {
    #pragma unroll
    for (int o = 16; o > 0; o >>= 1) v += __shfl_xor_sync(0xffffffffu, v, o);
    return v;
}

__global__ void __launch_bounds__(256)
sparsemax_kernel(const float* __restrict__ priors, float* __restrict__ out)
{
    const int lane = threadIdx.x & 31;
    const int row  = blockIdx.x * 8 + (threadIdx.x >> 5);
    const float* xr = g_x + (size_t)row * DIM;
    const float* pr = priors + (size_t)row * DIM;

    float z[64];
    float s = 0.f;
    #pragma unroll
    for (int i = 0; i < 64; ++i) {
        int j = lane + i * 32;
        z[i] = xr[j] * pr[j];
        s += z[i];
    }
    float tau = (warp_sum(s) - 1.f) * (1.f / (float)DIM);

    for (int it = 0; it < 40; ++it) {
        float ps = 0.f, pc = 0.f;
        #pragma unroll
        for (int i = 0; i < 64; ++i)
            if (z[i] > tau) { ps += z[i]; pc += 1.f; }
        ps = warp_sum(ps); pc = warp_sum(pc);
        float tn = (ps - 1.f) / pc;
        if (tn == tau) break;        // warp-uniform (same reduced values)
        tau = tn;
    }
    #pragma unroll
    for (int i = 0; i < 64; ++i) {
        int j = lane + i * 32;
        out[(size_t)row * DIM + j] = fmaxf(z[i] - tau, 0.f);
    }
}

// ================= launch =================
extern "C" void kernel_launch(void* const* d_in, const int* in_sizes, int n_in,
                              void* d_out, int out_size)
{
    const float* priors = (const float*)d_in[0];
    const float* feat   = (const float*)d_in[1];
    const float* fw     = (const float*)d_in[2];
    const float* gamma  = (const float*)d_in[3];
    const float* beta   = (const float*)d_in[4];
    float* out = (float*)d_out;

    static bool attr_set = false;
    if (!attr_set) {
        cudaFuncSetAttribute(gemm_bn_kernel, cudaFuncAttributeMaxDynamicSharedMemorySize, SMEM_TOTAL);
        attr_set = true;
    }

    split_kernel<<<(FEAT_N4 + W_N4 + 255) / 256, 256>>>(feat, fw);
    dim3 grid(DIM / TN, BATCH / TM);    // (8, 128); x fastest keeps W in L2
    gemm_bn_kernel<<<grid, 512, SMEM_TOTAL>>>(gamma, beta);
    sparsemax_kernel<<<BATCH / 8, 256>>>(priors, out);
}